// round 15
// baseline (speedup 1.0000x reference)
#include <cuda_runtime.h>
#include <cuda_bf16.h>
#include <cstdint>

namespace {
constexpr int kC = 256;
constexpr float kScale = 0.17677669529663687f;   // 32^-0.5
}

__device__ __nv_bfloat16 g_W[4 * kC * kC];       // Wq, Wk, Wv, Wp bf16

__device__ __forceinline__ uint32_t sptr(const void* p) {
  return (uint32_t)__cvta_generic_to_shared(p);
}
// XOR-swizzled address: rows are 512B (256 bf16). c = bf16 column (multiple of 8).
__device__ __forceinline__ uint32_t swz(uint32_t base, int r, int c) {
  return base + (uint32_t)(r * 512 + ((((c >> 3) ^ (r & 7))) << 4));
}
__device__ __forceinline__ void ldm4(uint32_t r[4], uint32_t a) {
  asm volatile("ldmatrix.sync.aligned.m8n8.x4.shared.b16 {%0,%1,%2,%3}, [%4];"
               : "=r"(r[0]), "=r"(r[1]), "=r"(r[2]), "=r"(r[3]) : "r"(a));
}
__device__ __forceinline__ void ldm4t(uint32_t r[4], uint32_t a) {
  asm volatile("ldmatrix.sync.aligned.m8n8.x4.trans.shared.b16 {%0,%1,%2,%3}, [%4];"
               : "=r"(r[0]), "=r"(r[1]), "=r"(r[2]), "=r"(r[3]) : "r"(a));
}
__device__ __forceinline__ void mma16816(float c[4], const uint32_t a[4], const uint32_t b[2]) {
  asm volatile("mma.sync.aligned.m16n8k16.row.col.f32.bf16.bf16.f32 "
               "{%0,%1,%2,%3}, {%4,%5,%6,%7}, {%8,%9}, {%0,%1,%2,%3};"
               : "+f"(c[0]), "+f"(c[1]), "+f"(c[2]), "+f"(c[3])
               : "r"(a[0]), "r"(a[1]), "r"(a[2]), "r"(a[3]), "r"(b[0]), "r"(b[1]));
}
__device__ __forceinline__ uint32_t packbf(float x, float y) {
  __nv_bfloat162 t = __floats2bfloat162_rn(x, y);
  return reinterpret_cast<uint32_t&>(t);
}
__device__ __forceinline__ void cpa16(uint32_t d, const void* s) {
  asm volatile("cp.async.cg.shared.global [%0], [%1], 16;" :: "r"(d), "l"(s));
}
__device__ __forceinline__ void cpa_commit() {
  asm volatile("cp.async.commit_group;" ::: "memory");
}

// ---------------- K0: weights fp32 -> bf16 (one matrix per blockIdx.y) ----------------
__global__ void k_convert(const float* __restrict__ Wq, const float* __restrict__ Wk,
                          const float* __restrict__ Wv, const float* __restrict__ Wp) {
  const float* src = (blockIdx.y == 0) ? Wq : (blockIdx.y == 1) ? Wk
                   : (blockIdx.y == 2) ? Wv : Wp;
  int i = (blockIdx.x * 256 + threadIdx.x) * 4;
  float4 a = *(const float4*)(src + i);
  *(uint2*)(g_W + blockIdx.y * (kC * kC) + i) = {packbf(a.x, a.y), packbf(a.z, a.w)};
}

// prefetch one 32x256 bf16 weight chunk (16KB) into swizzled buffer (128 threads)
__device__ __forceinline__ void prefetch_w(uint32_t uWb, const __nv_bfloat16* __restrict__ src,
                                           int tid) {
  #pragma unroll
  for (int j = 0; j < 8; j++) {
    int idx = tid + 128 * j;
    int row = idx >> 5, seg = idx & 31;
    cpa16(uWb + row * 512 + (((seg ^ (row & 7))) << 4), src + row * 256 + seg * 8);
  }
}

// chunk i: 0-7 Wq (head i), 8-15 Wk, 16-23 Wv, 24-31 Wp. 32 rows each.
__device__ __forceinline__ const __nv_bfloat16* wsrc(int i) {
  return (i < 8)  ? (g_W + i * 32 * kC)
       : (i < 16) ? (g_W + kC * kC + (i - 8) * 32 * kC)
       : (i < 24) ? (g_W + 2 * kC * kC + (i - 16) * 32 * kC)
                  : (g_W + 3 * kC * kC + (i - 24) * 32 * kC);
}

// ---------------- K2: LN + gather + Q/K/V proj + attention + out-proj + scatter ----------------
// 64 rows (1 window) per CTA, 128 threads (4 warps), 2 CTAs/SM.
// warp = (rg = w>>1 : 32 rows, ch = w&1 : 16-col half of 32-col chunk).
__global__ __launch_bounds__(128, 2) void k_fused(const float* __restrict__ inpt,
                                                  const int* __restrict__ pn,
                                                  const int* __restrict__ pt,
                                                  const float* __restrict__ gam,
                                                  const float* __restrict__ bet,
                                                  const float* __restrict__ bq,
                                                  const float* __restrict__ bk,
                                                  const float* __restrict__ bv,
                                                  const float* __restrict__ bp,
                                                  float* __restrict__ out) {
  extern __shared__ char smc[];
  const uint32_t uK = sptr(smc);             // 32KB: X -> K -> fp32 restage
  const uint32_t uV = uK + 32768;            // 32KB: Q-exchange -> V -> O
  const uint32_t uW[3] = {uK + 65536, uK + 81920, uK + 98304};  // 3x16KB weight bufs
  int* sDest = (int*)(smc + 114688);
  const int tid = threadIdx.x, w = tid >> 5, lane = tid & 31;
  const int rg = w >> 1, ch = w & 1;
  const int g = lane >> 2, tig = lane & 3;
  const int bN2 = ((lane >> 4) << 3) + (lane & 7), bK2 = ((lane >> 3) & 1) << 3;
  const int b2N = lane & 7, b2K = (lane >> 3) << 3;
  const int tK = (((lane >> 3) & 1) << 3) + (lane & 7), tN = (lane >> 4) << 3;
  const int aRow = lane & 15, aCol = (lane >> 4) << 3;

  prefetch_w(uW[0], wsrc(0), tid);
  cpa_commit();
  prefetch_w(uW[1], wsrc(1), tid);
  cpa_commit();

  if (tid < 64) {
    int m = blockIdx.x * 64 + tid;
    int ww = m >> 6, l = m & 63;
    int b = ww >> 9, rem = ww & 511;
    int n = (rem >> 6) * 8 + (l >> 3);
    int t = (rem & 63) * 8 + (l & 7);
    sDest[tid] = ((b * 64 + __ldg(pn + b * 64 + n)) * 512 + __ldg(pt + b * 512 + t)) * kC;
  }

  // ---- LN + gather: warp w handles rows [16w, 16w+16), 4 rows in flight ----
  {
    int c0 = lane * 8;
    float4 g0v = *(const float4*)(gam + c0);
    float4 g1v = *(const float4*)(gam + c0 + 4);
    float4 b0v = *(const float4*)(bet + c0);
    float4 b1v = *(const float4*)(bet + c0 + 4);
    const int mBase = blockIdx.x * 64 + 16 * w;
    #pragma unroll 1
    for (int rp = 0; rp < 4; rp++) {
      float4 p0[4], p1[4];
      #pragma unroll
      for (int r = 0; r < 4; r++) {
        int m = mBase + 4 * rp + r;
        int ww = m >> 6, l = m & 63;
        int b = ww >> 9, rem = ww & 511;
        int n = (rem >> 6) * 8 + (l >> 3);
        int t = (rem & 63) * 8 + (l & 7);
        const float* src = inpt + ((size_t)((b * 64 + __ldg(pn + b * 64 + n)) * 512
                                            + __ldg(pt + b * 512 + t))) * kC + c0;
        p0[r] = *(const float4*)(src);
        p1[r] = *(const float4*)(src + 4);
      }
      #pragma unroll
      for (int r = 0; r < 4; r++) {
        float s = p0[r].x + p0[r].y + p0[r].z + p0[r].w + p1[r].x + p1[r].y + p1[r].z + p1[r].w;
        float q = p0[r].x * p0[r].x + p0[r].y * p0[r].y + p0[r].z * p0[r].z + p0[r].w * p0[r].w
                + p1[r].x * p1[r].x + p1[r].y * p1[r].y + p1[r].z * p1[r].z + p1[r].w * p1[r].w;
        #pragma unroll
        for (int o = 16; o; o >>= 1) {
          s += __shfl_xor_sync(~0u, s, o);
          q += __shfl_xor_sync(~0u, q, o);
        }
        float mean = s * (1.f / 256.f);
        float inv = rsqrtf(q * (1.f / 256.f) - mean * mean + 1e-5f);
        uint4 rv;
        rv.x = packbf((p0[r].x - mean) * inv * g0v.x + b0v.x, (p0[r].y - mean) * inv * g0v.y + b0v.y);
        rv.y = packbf((p0[r].z - mean) * inv * g0v.z + b0v.z, (p0[r].w - mean) * inv * g0v.w + b0v.w);
        rv.z = packbf((p1[r].x - mean) * inv * g1v.x + b1v.x, (p1[r].y - mean) * inv * g1v.y + b1v.y);
        rv.w = packbf((p1[r].z - mean) * inv * g1v.z + b1v.z, (p1[r].w - mean) * inv * g1v.w + b1v.w);
        *(uint4*)(__cvta_shared_to_generic(swz(uK, 16 * w + 4 * rp + r, c0))) = rv;
      }
    }
  }
  // pair barrier: aF rows [32rg,32rg+32) written by warps 2rg, 2rg+1
  asm volatile("bar.sync %0, 64;" :: "r"(1 + rg) : "memory");
  uint32_t aF[2][16][4];
  #pragma unroll
  for (int rt = 0; rt < 2; rt++)
    #pragma unroll
    for (int ks = 0; ks < 16; ks++)
      ldm4(aF[rt][ks], swz(uK, 32 * rg + 16 * rt + aRow, ks * 16 + aCol));

  uint32_t aQall[4][2][2][4];   // [head-pair][row-tile][kstep][frag]

  // ---- chunks 0-23: Q (0-7, exchange via uV), K (8-15 -> uK), V (16-23 -> uV) ----
  #pragma unroll 1
  for (int i = 0; i < 24; i++) {
    asm volatile("cp.async.wait_group 1;" ::: "memory");
    __syncthreads();
    prefetch_w(uW[(i + 2) % 3], wsrc(i + 2), tid);
    cpa_commit();
    uint32_t uWb = uW[i % 3];
    if (i < 8) {
      // Q chunk = head h: warp computes rows 32rg x head-cols [16ch,16ch+16)
      const int h = i;
      float qc[2][2][4] = {};
      #pragma unroll
      for (int ks = 0; ks < 16; ks++) {
        uint32_t bb[4];
        ldm4(bb, swz(uWb, 16 * ch + bN2, ks * 16 + bK2));
        mma16816(qc[0][0], aF[0][ks], bb); mma16816(qc[0][1], aF[0][ks], bb + 2);
        mma16816(qc[1][0], aF[1][ks], bb); mma16816(qc[1][1], aF[1][ks], bb + 2);
      }
      uint32_t base = uV + h * 4096 + rg * 2048 + ch * 1024;
      #pragma unroll
      for (int rt = 0; rt < 2; rt++) {
        int col0 = h * 32 + ch * 16 + tig * 2;
        float e00 = __ldg(bq + col0),     e01 = __ldg(bq + col0 + 1);
        float e10 = __ldg(bq + col0 + 8), e11 = __ldg(bq + col0 + 9);
        uint4 mine;
        mine.x = packbf((qc[rt][0][0] + e00) * kScale, (qc[rt][0][1] + e01) * kScale);
        mine.y = packbf((qc[rt][0][2] + e00) * kScale, (qc[rt][0][3] + e01) * kScale);
        mine.z = packbf((qc[rt][1][0] + e10) * kScale, (qc[rt][1][1] + e11) * kScale);
        mine.w = packbf((qc[rt][1][2] + e10) * kScale, (qc[rt][1][3] + e11) * kScale);
        *(uint4*)(__cvta_shared_to_generic(base + rt * 512 + lane * 16)) = mine;
      }
      asm volatile("bar.sync %0, 64;" :: "r"(1 + rg) : "memory");
      if ((h & 1) == ch) {
        const int hp = h >> 1;
        #pragma unroll
        for (int rt = 0; rt < 2; rt++) {
          uint4 a0 = *(const uint4*)(__cvta_shared_to_generic(
              uV + h * 4096 + rg * 2048 + rt * 512 + lane * 16));           // ch=0 half (dims 0-15)
          uint4 a1 = *(const uint4*)(__cvta_shared_to_generic(
              uV + h * 4096 + rg * 2048 + 1024 + rt * 512 + lane * 16));    // ch=1 half (dims 16-31)
          aQall[hp][rt][0][0] = a0.x; aQall[hp][rt][0][1] = a0.y;
          aQall[hp][rt][0][2] = a0.z; aQall[hp][rt][0][3] = a0.w;
          aQall[hp][rt][1][0] = a1.x; aQall[hp][rt][1][1] = a1.y;
          aQall[hp][rt][1][2] = a1.z; aQall[hp][rt][1][3] = a1.w;
        }
      }
    } else {
      // K or V projection chunk
      const float* bias = (i < 16) ? bk : bv;
      uint32_t uOut = (i < 16) ? uK : uV;
      int cc = ((i < 16) ? (i - 8) : (i - 16)) * 32;
      float c[2][2][4] = {};
      #pragma unroll
      for (int ks = 0; ks < 16; ks++) {
        uint32_t bb[4];
        ldm4(bb, swz(uWb, 16 * ch + bN2, ks * 16 + bK2));
        mma16816(c[0][0], aF[0][ks], bb); mma16816(c[0][1], aF[0][ks], bb + 2);
        mma16816(c[1][0], aF[1][ks], bb); mma16816(c[1][1], aF[1][ks], bb + 2);
      }
      #pragma unroll
      for (int rt = 0; rt < 2; rt++) {
        #pragma unroll
        for (int nt = 0; nt < 2; nt++) {
          int col = cc + ch * 16 + nt * 8;
          float e0 = __ldg(bias + col + tig * 2), e1 = __ldg(bias + col + tig * 2 + 1);
          int m0 = 32 * rg + 16 * rt;
          *(uint32_t*)(__cvta_shared_to_generic(swz(uOut, m0 + g,     col) + tig * 4))
              = packbf(c[rt][nt][0] + e0, c[rt][nt][1] + e1);
          *(uint32_t*)(__cvta_shared_to_generic(swz(uOut, m0 + 8 + g, col) + tig * 4))
              = packbf(c[rt][nt][2] + e0, c[rt][nt][3] + e1);
        }
      }
    }
  }
  __syncthreads();   // K and V complete

  // ---- attention: warp (rg, ch): rows 32rg, heads {2hp+ch}; O over V in place ----
  #pragma unroll
  for (int hp = 0; hp < 4; hp++) {
    const int h = hp * 2 + ch;
    uint32_t bbK[8][4];
    #pragma unroll
    for (int nt = 0; nt < 8; nt++)
      ldm4(bbK[nt], swz(uK, nt * 8 + b2N, h * 32 + b2K));
    uint32_t aP[2][4][4];
    #pragma unroll
    for (int rt = 0; rt < 2; rt++) {
      float s[8][4];
      #pragma unroll
      for (int nt = 0; nt < 8; nt++) {
        s[nt][0] = s[nt][1] = s[nt][2] = s[nt][3] = 0.f;
        mma16816(s[nt], aQall[hp][rt][0], bbK[nt]);
        mma16816(s[nt], aQall[hp][rt][1], bbK[nt] + 2);
      }
      float sm0 = 0.f, sm1 = 0.f;
      #pragma unroll
      for (int nt = 0; nt < 8; nt++) {
        s[nt][0] = __expf(s[nt][0]); s[nt][1] = __expf(s[nt][1]);
        s[nt][2] = __expf(s[nt][2]); s[nt][3] = __expf(s[nt][3]);
        sm0 += s[nt][0] + s[nt][1]; sm1 += s[nt][2] + s[nt][3];
      }
      sm0 += __shfl_xor_sync(~0u, sm0, 1); sm0 += __shfl_xor_sync(~0u, sm0, 2);
      sm1 += __shfl_xor_sync(~0u, sm1, 1); sm1 += __shfl_xor_sync(~0u, sm1, 2);
      float r0 = __frcp_rn(sm0), r1 = __frcp_rn(sm1);
      #pragma unroll
      for (int kt = 0; kt < 4; kt++) {
        aP[rt][kt][0] = packbf(s[2 * kt][0] * r0, s[2 * kt][1] * r0);
        aP[rt][kt][1] = packbf(s[2 * kt][2] * r1, s[2 * kt][3] * r1);
        aP[rt][kt][2] = packbf(s[2 * kt + 1][0] * r0, s[2 * kt + 1][1] * r0);
        aP[rt][kt][3] = packbf(s[2 * kt + 1][2] * r1, s[2 * kt + 1][3] * r1);
      }
    }
    float o[2][4][4] = {};
    #pragma unroll
    for (int ks = 0; ks < 4; ks++) {
      uint32_t bb0[4], bb1[4];
      ldm4t(bb0, swz(uV, ks * 16 + tK, h * 32 + tN));
      ldm4t(bb1, swz(uV, ks * 16 + tK, h * 32 + 16 + tN));
      #pragma unroll
      for (int rt = 0; rt < 2; rt++) {
        mma16816(o[rt][0], aP[rt][ks], bb0); mma16816(o[rt][1], aP[rt][ks], bb0 + 2);
        mma16816(o[rt][2], aP[rt][ks], bb1); mma16816(o[rt][3], aP[rt][ks], bb1 + 2);
      }
    }
    // readers of head h's V cols = parity-ch warps {ch, 2+ch}
    asm volatile("bar.sync %0, 64;" :: "r"(3 + ch) : "memory");
    #pragma unroll
    for (int rt = 0; rt < 2; rt++) {
      int m0 = 32 * rg + 16 * rt;
      #pragma unroll
      for (int nt = 0; nt < 4; nt++) {
        *(uint32_t*)(__cvta_shared_to_generic(swz(uV, m0 + g,     h * 32 + nt * 8) + tig * 4))
            = packbf(o[rt][nt][0], o[rt][nt][1]);
        *(uint32_t*)(__cvta_shared_to_generic(swz(uV, m0 + 8 + g, h * 32 + nt * 8) + tig * 4))
            = packbf(o[rt][nt][2], o[rt][nt][3]);
      }
    }
  }
  __syncthreads();   // full O tile in uV
  #pragma unroll
  for (int rt = 0; rt < 2; rt++)
    #pragma unroll
    for (int ks = 0; ks < 16; ks++)
      ldm4(aF[rt][ks], swz(uV, 32 * rg + 16 * rt + aRow, ks * 16 + aCol));

  // ---- chunks 24-31: Wp -> fp32 restage (uK, rows of 144B) -> residual + scatter ----
  #pragma unroll 1
  for (int j = 0; j < 8; j++) {
    const int i = 24 + j;
    asm volatile("cp.async.wait_group 1;" ::: "memory");
    __syncthreads();
    if (i + 2 < 32) prefetch_w(uW[(i + 2) % 3], wsrc(i + 2), tid);
    cpa_commit();
    uint32_t uWb = uW[i % 3];
    const int cc = j * 32;
    float c[2][2][4] = {};
    #pragma unroll
    for (int ks = 0; ks < 16; ks++) {
      uint32_t bb[4];
      ldm4(bb, swz(uWb, 16 * ch + bN2, ks * 16 + bK2));
      mma16816(c[0][0], aF[0][ks], bb); mma16816(c[0][1], aF[0][ks], bb + 2);
      mma16816(c[1][0], aF[1][ks], bb); mma16816(c[1][1], aF[1][ks], bb + 2);
    }
    #pragma unroll
    for (int rt = 0; rt < 2; rt++) {
      #pragma unroll
      for (int nt = 0; nt < 2; nt++) {
        int lcol = ch * 16 + nt * 8 + tig * 2;
        float e0 = __ldg(bp + cc + lcol), e1 = __ldg(bp + cc + lcol + 1);
        int r0 = 32 * rg + 16 * rt + g, r1 = r0 + 8;
        *(float2*)(smc + r0 * 144 + lcol * 4) = {c[rt][nt][0] + e0, c[rt][nt][1] + e1};
        *(float2*)(smc + r1 * 144 + lcol * 4) = {c[rt][nt][2] + e0, c[rt][nt][3] + e1};
      }
    }
    __syncthreads();
    // coalesced residual + scatter: 64 rows x 32 fp32 cols
    #pragma unroll
    for (int jj = 0; jj < 4; jj++) {
      int idx = tid + 128 * jj;
      int row = idx >> 3, seg = idx & 7;
      float4 v = *(float4*)(smc + row * 144 + seg * 16);
      size_t d = (size_t)sDest[row] + cc + seg * 4;
      float4 iv = *(const float4*)(inpt + d);
      v.x += iv.x; v.y += iv.y; v.z += iv.z; v.w += iv.w;
      *(float4*)(out + d) = v;
    }
  }
}

extern "C" void kernel_launch(void* const* d_in, const int* in_sizes, int n_in,
                              void* d_out, int out_size) {
  const float* inpt = (const float*)d_in[0];
  const int*   pn   = (const int*)d_in[1];
  const int*   pt   = (const int*)d_in[2];
  const float* ln_g = (const float*)d_in[3];
  const float* ln_b = (const float*)d_in[4];
  const float* Wq   = (const float*)d_in[5];
  const float* bq   = (const float*)d_in[6];
  const float* Wk   = (const float*)d_in[7];
  const float* bk   = (const float*)d_in[8];
  const float* Wv   = (const float*)d_in[9];
  const float* bv   = (const float*)d_in[10];
  const float* Wp   = (const float*)d_in[11];
  const float* bp   = (const float*)d_in[12];
  float* out = (float*)d_out;
  (void)in_sizes; (void)n_in; (void)out_size;

  const int smem_fused = 114944;   // K(32K)+V(32K)+3x16K W+sDest -> 2 CTAs/SM
  cudaFuncSetAttribute(k_fused, cudaFuncAttributeMaxDynamicSharedMemorySize, smem_fused);

  k_convert<<<dim3(64, 4), 256>>>(Wq, Wk, Wv, Wp);
  k_fused<<<2048, 128, smem_fused>>>(inpt, pn, pt, ln_g, ln_b, bq, bk, bv, bp, out);
}

// round 16
// speedup vs baseline: 1.0567x; 1.0567x over previous
#include <cuda_runtime.h>
#include <cuda_bf16.h>
#include <cstdint>

namespace {
constexpr int kC = 256;
constexpr float kScale = 0.17677669529663687f;   // 32^-0.5
}

__device__ __nv_bfloat16 g_W[4 * kC * kC];       // Wv, Wk order handled via wsrc

__device__ __forceinline__ uint32_t sptr(const void* p) {
  return (uint32_t)__cvta_generic_to_shared(p);
}
// XOR-swizzled address: rows are 512B (256 bf16). c = bf16 column (multiple of 8).
__device__ __forceinline__ uint32_t swz(uint32_t base, int r, int c) {
  return base + (uint32_t)(r * 512 + ((((c >> 3) ^ (r & 7))) << 4));
}
__device__ __forceinline__ void ldm4(uint32_t r[4], uint32_t a) {
  asm volatile("ldmatrix.sync.aligned.m8n8.x4.shared.b16 {%0,%1,%2,%3}, [%4];"
               : "=r"(r[0]), "=r"(r[1]), "=r"(r[2]), "=r"(r[3]) : "r"(a));
}
__device__ __forceinline__ void ldm4t(uint32_t r[4], uint32_t a) {
  asm volatile("ldmatrix.sync.aligned.m8n8.x4.trans.shared.b16 {%0,%1,%2,%3}, [%4];"
               : "=r"(r[0]), "=r"(r[1]), "=r"(r[2]), "=r"(r[3]) : "r"(a));
}
__device__ __forceinline__ void stm4(uint32_t a, uint32_t r0, uint32_t r1,
                                     uint32_t r2, uint32_t r3) {
  asm volatile("stmatrix.sync.aligned.m8n8.x4.shared.b16 [%0], {%1,%2,%3,%4};"
               :: "r"(a), "r"(r0), "r"(r1), "r"(r2), "r"(r3) : "memory");
}
__device__ __forceinline__ void mma16816(float c[4], const uint32_t a[4], const uint32_t b[2]) {
  asm volatile("mma.sync.aligned.m16n8k16.row.col.f32.bf16.bf16.f32 "
               "{%0,%1,%2,%3}, {%4,%5,%6,%7}, {%8,%9}, {%0,%1,%2,%3};"
               : "+f"(c[0]), "+f"(c[1]), "+f"(c[2]), "+f"(c[3])
               : "r"(a[0]), "r"(a[1]), "r"(a[2]), "r"(a[3]), "r"(b[0]), "r"(b[1]));
}
__device__ __forceinline__ uint32_t packbf(float x, float y) {
  __nv_bfloat162 t = __floats2bfloat162_rn(x, y);
  return reinterpret_cast<uint32_t&>(t);
}
__device__ __forceinline__ void cpa16(uint32_t d, const void* s) {
  asm volatile("cp.async.cg.shared.global [%0], [%1], 16;" :: "r"(d), "l"(s));
}
__device__ __forceinline__ void cpa_commit() {
  asm volatile("cp.async.commit_group;" ::: "memory");
}

// ---------------- K0: weights fp32 -> bf16 (one matrix per blockIdx.y) ----------------
__global__ void k_convert(const float* __restrict__ Wq, const float* __restrict__ Wk,
                          const float* __restrict__ Wv, const float* __restrict__ Wp) {
  const float* src = (blockIdx.y == 0) ? Wq : (blockIdx.y == 1) ? Wk
                   : (blockIdx.y == 2) ? Wv : Wp;
  int i = (blockIdx.x * 256 + threadIdx.x) * 4;
  float4 a = *(const float4*)(src + i);
  *(uint2*)(g_W + blockIdx.y * (kC * kC) + i) = {packbf(a.x, a.y), packbf(a.z, a.w)};
}

// prefetch one 64x256 bf16 weight chunk (32KB) into swizzled buffer (256 threads)
__device__ __forceinline__ void prefetch_w64(uint32_t uWb, const __nv_bfloat16* __restrict__ src,
                                             int tid) {
  #pragma unroll
  for (int j = 0; j < 8; j++) {
    int idx = tid + 256 * j;
    int row = idx >> 5, seg = idx & 31;
    cpa16(uWb + row * 512 + (((seg ^ (row & 7))) << 4), src + row * 256 + seg * 8);
  }
}

// chunk order: 0-3 Wv, 4-7 Wk, 8-11 Wq (head pairs), 12-15 Wp. 64 rows each.
__device__ __forceinline__ const __nv_bfloat16* wsrc(int nx) {
  return (nx < 4)  ? (g_W + 2 * kC * kC + nx * 64 * kC)           // Wv
       : (nx < 8)  ? (g_W + kC * kC + (nx - 4) * 64 * kC)         // Wk
       : (nx < 12) ? (g_W + (nx - 8) * 64 * kC)                   // Wq
                   : (g_W + 3 * kC * kC + (nx - 12) * 64 * kC);   // Wp
}

// ---------------- K2: LN + gather + QKV proj + attention + out-proj + scatter ----------------
// 128 rows (2 windows) per CTA, 256 threads (8 warps).
// warp = (rg = w>>1 : 32 rows, ch = w&1 : 32-col half). A held in regs: 2 row-tiles x 16 ksteps.
__global__ __launch_bounds__(256, 1) void k_fused(const float* __restrict__ inpt,
                                                  const int* __restrict__ pn,
                                                  const int* __restrict__ pt,
                                                  const float* __restrict__ gam,
                                                  const float* __restrict__ bet,
                                                  const float* __restrict__ bq,
                                                  const float* __restrict__ bk,
                                                  const float* __restrict__ bv,
                                                  const float* __restrict__ bp,
                                                  float* __restrict__ out) {
  extern __shared__ char smc[];
  const uint32_t uK  = sptr(smc);            // 64KB: X staging -> projected K -> fp32 C restage
  const uint32_t uV  = uK + 65536;           // 64KB: projected V -> O (in place per head)
  const uint32_t uW[3] = {uK + 131072, uK + 163840, uK + 196608};  // 3x32KB weight bufs
  int* sDest = (int*)(smc + 229376);
  const int tid = threadIdx.x, w = tid >> 5, lane = tid & 31;
  const int rg = w >> 1, ch = w & 1;
  const int g = lane >> 2, tig = lane & 3;
  const int bN2 = ((lane >> 4) << 3) + (lane & 7), bK2 = ((lane >> 3) & 1) << 3;
  const int b2N = lane & 7, b2K = (lane >> 3) << 3;
  const int tK = (((lane >> 3) & 1) << 3) + (lane & 7), tN = (lane >> 4) << 3;
  const int aRow = lane & 15, aCol = (lane >> 4) << 3;

  // weight pipeline starts immediately (overlaps LN/gather)
  prefetch_w64(uW[0], wsrc(0), tid);
  cpa_commit();
  prefetch_w64(uW[1], wsrc(1), tid);
  cpa_commit();

  // scatter destinations for this CTA's 128 tokens
  if (tid < 128) {
    int m = blockIdx.x * 128 + tid;
    int ww = m >> 6, l = m & 63;
    int b = ww >> 9, rem = ww & 511;
    int n = (rem >> 6) * 8 + (l >> 3);
    int t = (rem & 63) * 8 + (l & 7);
    sDest[tid] = ((b * 64 + __ldg(pn + b * 64 + n)) * 512 + __ldg(pt + b * 512 + t)) * kC;
  }

  // ---- LN + gather: warp w handles rows [16w, 16w+16), 4 rows in flight ----
  {
    int c0 = lane * 8;
    float4 g0v = *(const float4*)(gam + c0);
    float4 g1v = *(const float4*)(gam + c0 + 4);
    float4 b0v = *(const float4*)(bet + c0);
    float4 b1v = *(const float4*)(bet + c0 + 4);
    const int mBase = blockIdx.x * 128 + 16 * w;
    #pragma unroll 1
    for (int rp = 0; rp < 4; rp++) {
      float4 p0[4], p1[4];
      #pragma unroll
      for (int r = 0; r < 4; r++) {
        int m = mBase + 4 * rp + r;
        int ww = m >> 6, l = m & 63;
        int b = ww >> 9, rem = ww & 511;
        int n = (rem >> 6) * 8 + (l >> 3);
        int t = (rem & 63) * 8 + (l & 7);
        const float* src = inpt + ((size_t)((b * 64 + __ldg(pn + b * 64 + n)) * 512
                                            + __ldg(pt + b * 512 + t))) * kC + c0;
        p0[r] = *(const float4*)(src);
        p1[r] = *(const float4*)(src + 4);
      }
      #pragma unroll
      for (int r = 0; r < 4; r++) {
        float s = p0[r].x + p0[r].y + p0[r].z + p0[r].w + p1[r].x + p1[r].y + p1[r].z + p1[r].w;
        float q = p0[r].x * p0[r].x + p0[r].y * p0[r].y + p0[r].z * p0[r].z + p0[r].w * p0[r].w
                + p1[r].x * p1[r].x + p1[r].y * p1[r].y + p1[r].z * p1[r].z + p1[r].w * p1[r].w;
        #pragma unroll
        for (int o = 16; o; o >>= 1) {
          s += __shfl_xor_sync(~0u, s, o);
          q += __shfl_xor_sync(~0u, q, o);
        }
        float mean = s * (1.f / 256.f);
        float inv = rsqrtf(q * (1.f / 256.f) - mean * mean + 1e-5f);
        uint4 rv;
        rv.x = packbf((p0[r].x - mean) * inv * g0v.x + b0v.x, (p0[r].y - mean) * inv * g0v.y + b0v.y);
        rv.y = packbf((p0[r].z - mean) * inv * g0v.z + b0v.z, (p0[r].w - mean) * inv * g0v.w + b0v.w);
        rv.z = packbf((p1[r].x - mean) * inv * g1v.x + b1v.x, (p1[r].y - mean) * inv * g1v.y + b1v.y);
        rv.w = packbf((p1[r].z - mean) * inv * g1v.z + b1v.z, (p1[r].w - mean) * inv * g1v.w + b1v.w);
        *(uint4*)(__cvta_shared_to_generic(swz(uK, 16 * w + 4 * rp + r, c0))) = rv;
      }
    }
  }
  // pair barrier: rows [32rg, 32rg+32) produced by warps 2rg, 2rg+1 only
  asm volatile("bar.sync %0, 64;" :: "r"(1 + rg) : "memory");
  // ---- extract this warp's A fragments: 2 row-tiles (rows 32rg, 32rg+16) x 16 ksteps ----
  uint32_t aF[2][16][4];
  #pragma unroll
  for (int rt = 0; rt < 2; rt++)
    #pragma unroll
    for (int ks = 0; ks < 16; ks++)
      ldm4(aF[rt][ks], swz(uK, 32 * rg + 16 * rt + aRow, ks * 16 + aCol));

  // ---- Phase A/B: V chunks 0-3 (-> uV), K chunks 4-7 (-> uK) ----
  // iter 0 has NO barrier: V0 writes uV while slow warps may still read X from uK.
  #pragma unroll 1
  for (int i = 0; i < 8; i++) {
    asm volatile("cp.async.wait_group 1;" ::: "memory");
    if (i) __syncthreads();
    int nx = i + 2;
    prefetch_w64(uW[nx % 3], wsrc(nx), tid);
    cpa_commit();
    uint32_t uWb = uW[i % 3];
    const float* bias = (i < 4) ? bv : bk;
    uint32_t uOut = (i < 4) ? uV : uK;
    int nc = i & 3;
    const int cb = ch * 32;
    float c[2][4][4] = {};
    #pragma unroll
    for (int ks = 0; ks < 16; ks++) {
      uint32_t bb0[4], bb1[4];
      ldm4(bb0, swz(uWb, cb + bN2,      ks * 16 + bK2));
      ldm4(bb1, swz(uWb, cb + 16 + bN2, ks * 16 + bK2));
      mma16816(c[0][0], aF[0][ks], bb0); mma16816(c[0][1], aF[0][ks], bb0 + 2);
      mma16816(c[0][2], aF[0][ks], bb1); mma16816(c[0][3], aF[0][ks], bb1 + 2);
      mma16816(c[1][0], aF[1][ks], bb0); mma16816(c[1][1], aF[1][ks], bb0 + 2);
      mma16816(c[1][2], aF[1][ks], bb1); mma16816(c[1][3], aF[1][ks], bb1 + 2);
    }
    #pragma unroll
    for (int rt = 0; rt < 2; rt++) {
      int m0 = 32 * rg + 16 * rt;
      #pragma unroll
      for (int np = 0; np < 2; np++) {           // 16-col pairs
        int colb = nc * 64 + ch * 32 + np * 16;
        float e0a = __ldg(bias + colb + tig * 2),     e1a = __ldg(bias + colb + tig * 2 + 1);
        float e0b = __ldg(bias + colb + 8 + tig * 2), e1b = __ldg(bias + colb + 8 + tig * 2 + 1);
        stm4(swz(uOut, m0 + aRow, colb + aCol),
             packbf(c[rt][2 * np][0] + e0a, c[rt][2 * np][1] + e1a),
             packbf(c[rt][2 * np][2] + e0a, c[rt][2 * np][3] + e1a),
             packbf(c[rt][2 * np + 1][0] + e0b, c[rt][2 * np + 1][1] + e1b),
             packbf(c[rt][2 * np + 1][2] + e0b, c[rt][2 * np + 1][3] + e1b));
      }
    }
  }

  // ---- Phase C: Q chunks 8-11, pack aQ into registers ----
  uint32_t aQall[4][2][2][4];   // [head-pair][row-tile][kstep][frag]
  #pragma unroll
  for (int hp = 0; hp < 4; hp++) {
    const int i = 8 + hp;
    asm volatile("cp.async.wait_group 1;" ::: "memory");
    __syncthreads();
    int nx = i + 2;
    if (nx < 16) prefetch_w64(uW[nx % 3], wsrc(nx), tid);
    cpa_commit();
    uint32_t uWb = uW[i % 3];
    const int cb = ch * 32;
    const int h = hp * 2 + ch;
    float qc[2][4][4] = {};
    #pragma unroll
    for (int ks = 0; ks < 16; ks++) {
      uint32_t bb0[4], bb1[4];
      ldm4(bb0, swz(uWb, cb + bN2,      ks * 16 + bK2));
      ldm4(bb1, swz(uWb, cb + 16 + bN2, ks * 16 + bK2));
      mma16816(qc[0][0], aF[0][ks], bb0); mma16816(qc[0][1], aF[0][ks], bb0 + 2);
      mma16816(qc[0][2], aF[0][ks], bb1); mma16816(qc[0][3], aF[0][ks], bb1 + 2);
      mma16816(qc[1][0], aF[1][ks], bb0); mma16816(qc[1][1], aF[1][ks], bb0 + 2);
      mma16816(qc[1][2], aF[1][ks], bb1); mma16816(qc[1][3], aF[1][ks], bb1 + 2);
    }
    #pragma unroll
    for (int rt = 0; rt < 2; rt++) {
      #pragma unroll
      for (int kt = 0; kt < 2; kt++) {
        #pragma unroll
        for (int j = 0; j < 2; j++) {
          int nt = 2 * kt + j;
          int col = h * 32 + nt * 8 + tig * 2;
          float e0 = __ldg(bq + col), e1 = __ldg(bq + col + 1);
          aQall[hp][rt][kt][2 * j]     = packbf((qc[rt][nt][0] + e0) * kScale,
                                                (qc[rt][nt][1] + e1) * kScale);
          aQall[hp][rt][kt][2 * j + 1] = packbf((qc[rt][nt][2] + e0) * kScale,
                                                (qc[rt][nt][3] + e1) * kScale);
        }
      }
    }
  }

  // ---- attention: warp (rg, ch): rows 32rg, heads {2hp+ch}; O over V in place ----
  {
    const int wi = rg >> 1;              // window
    const int barid = 1 + 2 * wi + ch;   // 2-warp (window, parity) group, 64 threads
    #pragma unroll
    for (int hp = 0; hp < 4; hp++) {
      const int h = hp * 2 + ch;
      uint32_t bbK[8][4];
      #pragma unroll
      for (int nt = 0; nt < 8; nt++)
        ldm4(bbK[nt], swz(uK, 64 * wi + nt * 8 + b2N, h * 32 + b2K));
      uint32_t aP[2][4][4];
      #pragma unroll
      for (int rt = 0; rt < 2; rt++) {
        float s[8][4];
        #pragma unroll
        for (int nt = 0; nt < 8; nt++) {
          s[nt][0] = s[nt][1] = s[nt][2] = s[nt][3] = 0.f;
          mma16816(s[nt], aQall[hp][rt][0], bbK[nt]);
          mma16816(s[nt], aQall[hp][rt][1], bbK[nt] + 2);
        }
        float sm0 = 0.f, sm1 = 0.f;
        #pragma unroll
        for (int nt = 0; nt < 8; nt++) {
          s[nt][0] = __expf(s[nt][0]); s[nt][1] = __expf(s[nt][1]);
          s[nt][2] = __expf(s[nt][2]); s[nt][3] = __expf(s[nt][3]);
          sm0 += s[nt][0] + s[nt][1]; sm1 += s[nt][2] + s[nt][3];
        }
        sm0 += __shfl_xor_sync(~0u, sm0, 1); sm0 += __shfl_xor_sync(~0u, sm0, 2);
        sm1 += __shfl_xor_sync(~0u, sm1, 1); sm1 += __shfl_xor_sync(~0u, sm1, 2);
        float r0 = __frcp_rn(sm0), r1 = __frcp_rn(sm1);
        #pragma unroll
        for (int kt = 0; kt < 4; kt++) {
          aP[rt][kt][0] = packbf(s[2 * kt][0] * r0, s[2 * kt][1] * r0);
          aP[rt][kt][1] = packbf(s[2 * kt][2] * r1, s[2 * kt][3] * r1);
          aP[rt][kt][2] = packbf(s[2 * kt + 1][0] * r0, s[2 * kt + 1][1] * r0);
          aP[rt][kt][3] = packbf(s[2 * kt + 1][2] * r1, s[2 * kt + 1][3] * r1);
        }
      }
      float o[2][4][4] = {};
      #pragma unroll
      for (int ks = 0; ks < 4; ks++) {
        uint32_t bb0[4], bb1[4];
        ldm4t(bb0, swz(uV, 64 * wi + ks * 16 + tK, h * 32 + tN));
        ldm4t(bb1, swz(uV, 64 * wi + ks * 16 + tK, h * 32 + 16 + tN));
        #pragma unroll
        for (int rt = 0; rt < 2; rt++) {
          mma16816(o[rt][0], aP[rt][ks], bb0); mma16816(o[rt][1], aP[rt][ks], bb0 + 2);
          mma16816(o[rt][2], aP[rt][ks], bb1); mma16816(o[rt][3], aP[rt][ks], bb1 + 2);
        }
      }
      // both warps of this (window, parity) group done READING V cols h*32..h*32+32
      asm volatile("bar.sync %0, 64;" :: "r"(barid) : "memory");
      #pragma unroll
      for (int rt = 0; rt < 2; rt++) {
        int m0 = 32 * rg + 16 * rt;
        stm4(swz(uV, m0 + aRow, h * 32 + aCol),
             packbf(o[rt][0][0], o[rt][0][1]), packbf(o[rt][0][2], o[rt][0][3]),
             packbf(o[rt][1][0], o[rt][1][1]), packbf(o[rt][1][2], o[rt][1][3]));
        stm4(swz(uV, m0 + aRow, h * 32 + 16 + aCol),
             packbf(o[rt][2][0], o[rt][2][1]), packbf(o[rt][2][2], o[rt][2][3]),
             packbf(o[rt][3][0], o[rt][3][1]), packbf(o[rt][3][2], o[rt][3][3]));
      }
    }
  }
  __syncthreads();   // full O tile visible in uV
  #pragma unroll
  for (int rt = 0; rt < 2; rt++)
    #pragma unroll
    for (int ks = 0; ks < 16; ks++)
      ldm4(aF[rt][ks], swz(uV, 32 * rg + 16 * rt + aRow, ks * 16 + aCol));

  // ---- Phase D: Wp chunks 12-15 -> fp32 restage in uK -> residual + scatter ----
  #pragma unroll 1
  for (int j = 0; j < 4; j++) {
    const int i = 12 + j;
    if (i >= 14) asm volatile("cp.async.wait_group 0;" ::: "memory");
    else         asm volatile("cp.async.wait_group 1;" ::: "memory");
    __syncthreads();
    int nx = i + 2;
    if (nx < 16) prefetch_w64(uW[nx % 3], wsrc(nx), tid);
    cpa_commit();
    uint32_t uWb = uW[i % 3];
    const int cb = ch * 32;
    float c[2][4][4] = {};
    #pragma unroll
    for (int ks = 0; ks < 16; ks++) {
      uint32_t bb0[4], bb1[4];
      ldm4(bb0, swz(uWb, cb + bN2,      ks * 16 + bK2));
      ldm4(bb1, swz(uWb, cb + 16 + bN2, ks * 16 + bK2));
      mma16816(c[0][0], aF[0][ks], bb0); mma16816(c[0][1], aF[0][ks], bb0 + 2);
      mma16816(c[0][2], aF[0][ks], bb1); mma16816(c[0][3], aF[0][ks], bb1 + 2);
      mma16816(c[1][0], aF[1][ks], bb0); mma16816(c[1][1], aF[1][ks], bb0 + 2);
      mma16816(c[1][2], aF[1][ks], bb1); mma16816(c[1][3], aF[1][ks], bb1 + 2);
    }
    // restage: fp32 rows of 64 cols, stride 272B, in uK region
    #pragma unroll
    for (int rt = 0; rt < 2; rt++) {
      #pragma unroll
      for (int nt = 0; nt < 4; nt++) {
        int lcol = ch * 32 + nt * 8 + tig * 2;
        float e0 = __ldg(bp + j * 64 + lcol), e1 = __ldg(bp + j * 64 + lcol + 1);
        int r0 = 32 * rg + 16 * rt + g, r1 = r0 + 8;
        *(float2*)(smc + r0 * 272 + lcol * 4) = {c[rt][nt][0] + e0, c[rt][nt][1] + e1};
        *(float2*)(smc + r1 * 272 + lcol * 4) = {c[rt][nt][2] + e0, c[rt][nt][3] + e1};
      }
    }
    __syncthreads();
    // coalesced residual + scatter: 128 rows x 64 fp32 cols
    #pragma unroll
    for (int jj = 0; jj < 8; jj++) {
      int idx = tid + 256 * jj;
      int row = idx >> 4, seg = idx & 15;
      float4 v = *(float4*)(smc + row * 272 + seg * 16);
      size_t d = (size_t)sDest[row] + j * 64 + seg * 4;
      float4 iv = *(const float4*)(inpt + d);
      v.x += iv.x; v.y += iv.y; v.z += iv.z; v.w += iv.w;
      *(float4*)(out + d) = v;
    }
  }
}

extern "C" void kernel_launch(void* const* d_in, const int* in_sizes, int n_in,
                              void* d_out, int out_size) {
  const float* inpt = (const float*)d_in[0];
  const int*   pn   = (const int*)d_in[1];
  const int*   pt   = (const int*)d_in[2];
  const float* ln_g = (const float*)d_in[3];
  const float* ln_b = (const float*)d_in[4];
  const float* Wq   = (const float*)d_in[5];
  const float* bq   = (const float*)d_in[6];
  const float* Wk   = (const float*)d_in[7];
  const float* bk   = (const float*)d_in[8];
  const float* Wv   = (const float*)d_in[9];
  const float* bv   = (const float*)d_in[10];
  const float* Wp   = (const float*)d_in[11];
  const float* bp   = (const float*)d_in[12];
  float* out = (float*)d_out;
  (void)in_sizes; (void)n_in; (void)out_size;

  const int smem_fused = 229888;           // K(64K)+V(64K)+3xW(96K)+sDest
  cudaFuncSetAttribute(k_fused, cudaFuncAttributeMaxDynamicSharedMemorySize, smem_fused);

  k_convert<<<dim3(64, 4), 256>>>(Wq, Wk, Wv, Wp);
  k_fused<<<1024, 256, smem_fused>>>(inpt, pn, pt, ln_g, ln_b, bq, bk, bv, bp, out);
}